// round 11
// baseline (speedup 1.0000x reference)
#include <cuda_runtime.h>
#include <cuda_fp16.h>
#include <cstdint>

// BERTEmbedding: out[b,l,:] = token_table[seq[b,l],:]
//                           + mean_{g<cnt}(genre_table[gids[seq[b,l],g],:])
//                           + pos_table[l,:]
//
// R11: minimize MEMORY-INSTRUCTION count per token (LSU accept-rate model).
//  - warp = 4 tokens sharing l (b, b+64, b+128, b+192): pos 1 load / 4 tokens,
//    seq + gcnt lane-parallel (1 instr each / 4 tokens).
//  - tgid row (32B) via one ld.global.v8.b32.
//  - genre table as fp16 in smem (5.25KB/CTA), LDS.64 reads, half2 accumulate.
//  - token-table loads keep L2 evict_last hint; output st.global.cs (R10 win).

#define SEQ_L 200
#define MAX_G 8
#define N_GENRE 21
#define NUM_TOKENS (256 * 200)
#define TOK_PER_WARP 4
#define BSTRIDE 64                                  // b, b+64, b+128, b+192
#define BLOCK_THREADS 256
#define WARPS_TOTAL (NUM_TOKENS / TOK_PER_WARP)     // 12800
#define GRID_BLOCKS (WARPS_TOTAL / (BLOCK_THREADS / 32))  // 1600

__device__ __forceinline__ uint64_t mk_evict_last_policy() {
    uint64_t pol;
    asm("createpolicy.fractional.L2::evict_last.b64 %0, 1.0;" : "=l"(pol));
    return pol;
}
__device__ __forceinline__ float4 ldg_hint(const float4* p, uint64_t pol) {
    float4 v;
    asm volatile("ld.global.nc.L2::cache_hint.v4.f32 {%0,%1,%2,%3}, [%4], %5;"
                 : "=f"(v.x), "=f"(v.y), "=f"(v.z), "=f"(v.w)
                 : "l"(p), "l"(pol));
    return v;
}
__device__ __forceinline__ void stg_cs(float4* p, float4 v) {
    asm volatile("st.global.cs.v4.f32 [%0], {%1,%2,%3,%4};"
                 :: "l"(p), "f"(v.x), "f"(v.y), "f"(v.z), "f"(v.w) : "memory");
}

__global__ __launch_bounds__(BLOCK_THREADS) void bert_embed_kernel(
    const int* __restrict__ seq,          // [256*200]
    const float4* __restrict__ tok_tab,   // [VOCAB,32]
    const float4* __restrict__ gen_tab,   // [21,32]
    const float4* __restrict__ pos_tab,   // [200,32]
    const int* __restrict__ tgid,         // [VOCAB,8]
    const int* __restrict__ gcnt,         // [VOCAB]
    float4* __restrict__ out)             // [256*200,32]
{
    // Genre table as fp16: row r, dim-pair q -> s_gen[r*64 + q]; 5.25 KB.
    __shared__ __align__(16) uint32_t s_gen[N_GENRE * 64];

    for (int i = threadIdx.x; i < N_GENRE * 32; i += BLOCK_THREADS) {
        const float4 v = __ldg(&gen_tab[i]);
        __half2 a = __floats2half2_rn(v.x, v.y);
        __half2 b = __floats2half2_rn(v.z, v.w);
        s_gen[i * 2 + 0] = *reinterpret_cast<unsigned*>(&a);
        s_gen[i * 2 + 1] = *reinterpret_cast<unsigned*>(&b);
    }
    __syncthreads();

    const int lane = threadIdx.x & 31;
    const int wlin = (blockIdx.x * BLOCK_THREADS + threadIdx.x) >> 5;  // 0..12799
    const int bgrp = wlin / SEQ_L;        // 0..63
    const int l    = wlin % SEQ_L;

    const uint64_t pol = mk_evict_last_policy();

    // Lane-parallel metadata for the warp's 4 tokens (lanes j, j+4, ... replicate).
    const int sid   = (bgrp + BSTRIDE * (lane & 3)) * SEQ_L + l;
    const int t_pre = __ldg(&seq[sid]);
    const int c_pre = __ldg(&gcnt[t_pre]);
    const float inv_pre = 1.0f / (float)c_pre;

    // Pos row shared by all 4 tokens (same l).
    const float4 pos = __ldg(&pos_tab[l * 32 + lane]);

    #pragma unroll
    for (int j = 0; j < TOK_PER_WARP; j++) {
        const int   t   = __shfl_sync(0xffffffffu, t_pre, j);
        const int   cnt = __shfl_sync(0xffffffffu, c_pre, j);
        const float inv = __shfl_sync(0xffffffffu, inv_pre, j);

        // All 8 genre ids in ONE 256-bit load (32B row, 32B-aligned).
        int g0, g1, g2, g3, g4, g5, g6, g7;
        asm volatile("ld.global.v8.b32 {%0,%1,%2,%3,%4,%5,%6,%7}, [%8];"
                     : "=r"(g0), "=r"(g1), "=r"(g2), "=r"(g3),
                       "=r"(g4), "=r"(g5), "=r"(g6), "=r"(g7)
                     : "l"(tgid + (size_t)t * MAX_G));
        const int gg[MAX_G] = {g0, g1, g2, g3, g4, g5, g6, g7};

        const float4 tok = ldg_hint(&tok_tab[(size_t)t * 32 + lane], pol);

        // Genre accumulation from fp16 smem; half2 adds (2 per row).
        __half2 s01 = __float2half2_rn(0.f);
        __half2 s23 = __float2half2_rn(0.f);
        #pragma unroll
        for (int g = 0; g < MAX_G; g++) {
            if (g < cnt) {                         // warp-uniform predicate
                const uint2 ge = *reinterpret_cast<const uint2*>(
                    &s_gen[gg[g] * 64 + lane * 2]);      // LDS.64, conflict-free
                s01 = __hadd2(s01, *reinterpret_cast<const __half2*>(&ge.x));
                s23 = __hadd2(s23, *reinterpret_cast<const __half2*>(&ge.y));
            }
        }

        const float2 f01 = __half22float2(s01);
        const float2 f23 = __half22float2(s23);

        float4 o;
        o.x = tok.x + pos.x + f01.x * inv;
        o.y = tok.y + pos.y + f01.y * inv;
        o.z = tok.z + pos.z + f23.x * inv;
        o.w = tok.w + pos.w + f23.y * inv;

        const int oidx = (bgrp + BSTRIDE * j) * SEQ_L + l;
        stg_cs(&out[(size_t)oidx * 32 + lane], o);
    }
}

extern "C" void kernel_launch(void* const* d_in, const int* in_sizes, int n_in,
                              void* d_out, int out_size) {
    const int*    seq     = (const int*)d_in[0];
    const float4* tok_tab = (const float4*)d_in[1];
    const float4* gen_tab = (const float4*)d_in[2];
    const float4* pos_tab = (const float4*)d_in[3];
    const int*    tgid    = (const int*)d_in[4];
    const int*    gcnt    = (const int*)d_in[5];
    float4*       out     = (float4*)d_out;

    bert_embed_kernel<<<GRID_BLOCKS, BLOCK_THREADS>>>(
        seq, tok_tab, gen_tab, pos_tab, tgid, gcnt, out);
}

// round 12
// speedup vs baseline: 1.0151x; 1.0151x over previous
#include <cuda_runtime.h>
#include <cstdint>

// BERTEmbedding: out[b,l,:] = token_table[seq[b,l],:]
//                           + mean_{g<cnt}(genre_table[gids[seq[b,l],g],:])
//                           + pos_table[l,:]
//
// R12: depth-8 gather batching per warp to collapse the dependent chain
// seq -> t -> {tok,tgid} -> genre into ONE exposed L2 round trip.
//  Phase A: lane-parallel metadata (seq, gcnt, inv for 8 tokens in 3 instrs;
//           all 8 gid rows via lane-parallel int4 in 1 instr).
//  Phase B: all 8 token-row gathers issued back-to-back (8 in flight/warp).
//  Phase C: accumulate; genre rows L1-hot; gids via shfl (no global dep).
//  L2 evict_last on token gathers AND output stores (keep both resident
//  across graph replays; R10 showed reads already L2-hit).
// Warp = 8 tokens sharing l (pos loaded once); b = bg + 32*j.

#define SEQ_L 200
#define MAX_G 8
#define TOKPW 8
#define BSTRIDE 32
#define BLOCK_THREADS 256
#define NUM_TOKENS (256 * 200)
#define WARPS_TOTAL (NUM_TOKENS / TOKPW)                  // 6400
#define GRID_BLOCKS (WARPS_TOTAL / (BLOCK_THREADS / 32))  // 800

__device__ __forceinline__ uint64_t mk_evict_last_policy() {
    uint64_t pol;
    asm("createpolicy.fractional.L2::evict_last.b64 %0, 1.0;" : "=l"(pol));
    return pol;
}
__device__ __forceinline__ float4 ldg_hint(const float4* p, uint64_t pol) {
    float4 v;
    asm volatile("ld.global.nc.L2::cache_hint.v4.f32 {%0,%1,%2,%3}, [%4], %5;"
                 : "=f"(v.x), "=f"(v.y), "=f"(v.z), "=f"(v.w)
                 : "l"(p), "l"(pol));
    return v;
}
__device__ __forceinline__ void stg_hint(float4* p, float4 v, uint64_t pol) {
    asm volatile("st.global.L2::cache_hint.v4.f32 [%0], {%1,%2,%3,%4}, %5;"
                 :: "l"(p), "f"(v.x), "f"(v.y), "f"(v.z), "f"(v.w), "l"(pol)
                 : "memory");
}

__global__ __launch_bounds__(BLOCK_THREADS) void bert_embed_kernel(
    const int* __restrict__ seq,          // [256*200]
    const float4* __restrict__ tok_tab,   // [VOCAB,32]
    const float4* __restrict__ gen_tab,   // [21,32]
    const float4* __restrict__ pos_tab,   // [200,32]
    const int4* __restrict__ tgid,        // [VOCAB,8] as [VOCAB,2] int4
    const int* __restrict__ gcnt,         // [VOCAB]
    float4* __restrict__ out)             // [256*200,32]
{
    const int lane = threadIdx.x & 31;
    const int wlin = (blockIdx.x * BLOCK_THREADS + threadIdx.x) >> 5;  // 0..6399
    const int bg   = wlin / SEQ_L;        // 0..31
    const int l    = wlin % SEQ_L;

    const uint64_t pol = mk_evict_last_policy();
    const unsigned FULL = 0xffffffffu;

    // ---- Phase A: lane-parallel metadata (one L2 round trip) ----
    const int jA   = lane & (TOKPW - 1);
    const int sidA = (bg + BSTRIDE * jA) * SEQ_L + l;
    const int t_pre = __ldg(&seq[sidA]);
    const int c_pre = __ldg(&gcnt[t_pre]);
    const float inv_pre = 1.0f / (float)c_pre;

    // lanes: h = lane&1 selects int4 half, jg = (lane>>1)&7 selects token
    const int jg = (lane >> 1) & (TOKPW - 1);
    const int h  = lane & 1;
    const int t_for_gid = __shfl_sync(FULL, t_pre, jg);
    const int4 gid4_pre = __ldg(&tgid[t_for_gid * 2 + h]);

    // pos row: shared by all 8 tokens (same l)
    const float4 pos = __ldg(&pos_tab[l * 32 + lane]);

    // ---- Phase B: all 8 token-row gathers in flight ----
    int tj[TOKPW];
    #pragma unroll
    for (int j = 0; j < TOKPW; j++) tj[j] = __shfl_sync(FULL, t_pre, j);

    float4 tok[TOKPW];
    #pragma unroll
    for (int j = 0; j < TOKPW; j++)
        tok[j] = ldg_hint(&tok_tab[(size_t)tj[j] * 32 + lane], pol);

    // ---- Phase C: accumulate + store ----
    #pragma unroll
    for (int j = 0; j < TOKPW; j++) {
        const int   cnt = __shfl_sync(FULL, c_pre, j);
        const float inv = __shfl_sync(FULL, inv_pre, j);

        // gids for token j live in lanes 2j (first 4) and 2j+1 (last 4)
        const int gid[MAX_G] = {
            __shfl_sync(FULL, gid4_pre.x, 2 * j),
            __shfl_sync(FULL, gid4_pre.y, 2 * j),
            __shfl_sync(FULL, gid4_pre.z, 2 * j),
            __shfl_sync(FULL, gid4_pre.w, 2 * j),
            __shfl_sync(FULL, gid4_pre.x, 2 * j + 1),
            __shfl_sync(FULL, gid4_pre.y, 2 * j + 1),
            __shfl_sync(FULL, gid4_pre.z, 2 * j + 1),
            __shfl_sync(FULL, gid4_pre.w, 2 * j + 1)
        };

        float4 s = make_float4(0.f, 0.f, 0.f, 0.f);
        #pragma unroll
        for (int g = 0; g < MAX_G; g++) {
            if (g < cnt) {                         // warp-uniform predicate
                const float4 ge = __ldg(&gen_tab[gid[g] * 32 + lane]); // L1-hot
                s.x += ge.x; s.y += ge.y; s.z += ge.z; s.w += ge.w;
            }
        }

        float4 o;
        o.x = tok[j].x + pos.x + s.x * inv;
        o.y = tok[j].y + pos.y + s.y * inv;
        o.z = tok[j].z + pos.z + s.z * inv;
        o.w = tok[j].w + pos.w + s.w * inv;

        const int oidx = (bg + BSTRIDE * j) * SEQ_L + l;
        stg_hint(&out[(size_t)oidx * 32 + lane], o, pol);
    }
}

extern "C" void kernel_launch(void* const* d_in, const int* in_sizes, int n_in,
                              void* d_out, int out_size) {
    const int*    seq     = (const int*)d_in[0];
    const float4* tok_tab = (const float4*)d_in[1];
    const float4* gen_tab = (const float4*)d_in[2];
    const float4* pos_tab = (const float4*)d_in[3];
    const int4*   tgid    = (const int4*)d_in[4];
    const int*    gcnt    = (const int*)d_in[5];
    float4*       out     = (float4*)d_out;

    bert_embed_kernel<<<GRID_BLOCKS, BLOCK_THREADS>>>(
        seq, tok_tab, gen_tab, pos_tab, tgid, gcnt, out);
}

// round 13
// speedup vs baseline: 1.0173x; 1.0022x over previous
#include <cuda_runtime.h>
#include <cstdint>

// BERTEmbedding: out[b,l,:] = token_table[seq[b,l],:]
//                           + mean_{g<cnt}(genre_table[gids[seq[b,l],g],:])
//                           + pos_table[l,:]
//
// R13: cache-placement refinement of the best variant (R10).
//  - token-table gathers: ld.global.nc.L1::no_allocate.L2::cache_hint
//    (evict_last policy). Rows have ~1.28x reuse -> don't pollute L1;
//    pin in L2 across graph replays.
//  - output: st.global.cs (streaming, evict-first).
//  - pos/genre/meta: default L1 caching (these have high reuse and now get
//    the whole L1).
//  - 512-thread blocks (3200 CTAs), warp per token, lane k owns dims 4k..4k+3.

#define NUM_TOKENS (256 * 200)
#define SEQ_L 200
#define MAX_G 8
#define BLOCK_THREADS 512
#define GRID_BLOCKS (NUM_TOKENS / (BLOCK_THREADS / 32))   // 3200

__device__ __forceinline__ uint64_t mk_evict_last_policy() {
    uint64_t pol;
    asm("createpolicy.fractional.L2::evict_last.b64 %0, 1.0;" : "=l"(pol));
    return pol;
}
__device__ __forceinline__ float4 ldg_tok(const float4* p, uint64_t pol) {
    float4 v;
    asm volatile(
        "ld.global.nc.L1::no_allocate.L2::cache_hint.v4.f32 {%0,%1,%2,%3}, [%4], %5;"
        : "=f"(v.x), "=f"(v.y), "=f"(v.z), "=f"(v.w)
        : "l"(p), "l"(pol));
    return v;
}
__device__ __forceinline__ void stg_cs(float4* p, float4 v) {
    asm volatile("st.global.cs.v4.f32 [%0], {%1,%2,%3,%4};"
                 :: "l"(p), "f"(v.x), "f"(v.y), "f"(v.z), "f"(v.w) : "memory");
}

__global__ __launch_bounds__(BLOCK_THREADS) void bert_embed_kernel(
    const int* __restrict__ seq,          // [256*200]
    const float4* __restrict__ tok_tab,   // [VOCAB,32]
    const float4* __restrict__ gen_tab,   // [21,32]
    const float4* __restrict__ pos_tab,   // [200,32]
    const int4* __restrict__ tgid,        // [VOCAB,8] as [VOCAB,2] int4
    const int* __restrict__ gcnt,         // [VOCAB]
    float4* __restrict__ out)             // [256*200,32]
{
    const int warp = (blockIdx.x * BLOCK_THREADS + threadIdx.x) >> 5;
    const int lane = threadIdx.x & 31;

    const uint64_t pol = mk_evict_last_policy();

    const int l = warp % SEQ_L;
    const int t = __ldg(&seq[warp]);               // warp-uniform

    // Independent level-2 loads, back-to-back for MLP.
    const int    cnt = __ldg(&gcnt[t]);            // warp-uniform
    const int4   ga  = __ldg(&tgid[t * 2]);        // warp-uniform
    const int4   gb  = __ldg(&tgid[t * 2 + 1]);    // warp-uniform
    const float4 tok = ldg_tok(&tok_tab[(size_t)t * 32 + lane], pol);
    const float4 pos = __ldg(&pos_tab[l * 32 + lane]);   // L1-resident

    const int gid[MAX_G] = {ga.x, ga.y, ga.z, ga.w, gb.x, gb.y, gb.z, gb.w};

    float4 s = make_float4(0.f, 0.f, 0.f, 0.f);
    #pragma unroll
    for (int g = 0; g < MAX_G; g++) {
        if (g < cnt) {                              // warp-uniform predicate
            const float4 ge = __ldg(&gen_tab[gid[g] * 32 + lane]);  // L1-hot
            s.x += ge.x; s.y += ge.y; s.z += ge.z; s.w += ge.w;
        }
    }

    const float inv = 1.0f / (float)cnt;
    float4 o;
    o.x = tok.x + pos.x + s.x * inv;
    o.y = tok.y + pos.y + s.y * inv;
    o.z = tok.z + pos.z + s.z * inv;
    o.w = tok.w + pos.w + s.w * inv;

    // Streaming store: evict-first, don't churn the table out of L2.
    stg_cs(&out[(size_t)warp * 32 + lane], o);
}

extern "C" void kernel_launch(void* const* d_in, const int* in_sizes, int n_in,
                              void* d_out, int out_size) {
    const int*    seq     = (const int*)d_in[0];
    const float4* tok_tab = (const float4*)d_in[1];
    const float4* gen_tab = (const float4*)d_in[2];
    const float4* pos_tab = (const float4*)d_in[3];
    const int4*   tgid    = (const int4*)d_in[4];
    const int*    gcnt    = (const int*)d_in[5];
    float4*       out     = (float4*)d_out;

    bert_embed_kernel<<<GRID_BLOCKS, BLOCK_THREADS>>>(
        seq, tok_tab, gen_tab, pos_tab, tgid, gcnt, out);
}